// round 12
// baseline (speedup 1.0000x reference)
#include <cuda_runtime.h>
#include <cuda_fp16.h>
#include <math.h>
#include <stdint.h>

typedef unsigned long long u64;

#define NN 3072
#define CA 128
#define CS 384
#define CZ 16
#define NH 4
#define DH 32
#define CF 256
#define LNEPS 1e-5f
#define LOG2E 1.4426950408889634f

#define TQ 32
#define TK 32
#define NSPLIT 8
#define KPS (NN / NSPLIT)
#define NT (KPS / TK)
#define NSTG 4
#define KSTRH 136
#define VSTRH 40
#define BSTR8 48        // bytes per bias row in smem (32 data + 16 pad, 16B aligned)
#define PSTRH 40
#define ATHREADS 256

// ---------------- scratch ----------------
static __device__ float g_sn[NN*CS];
static __device__ float g_h[NN*CA];
static __device__ float g_h2[NN*CA];
static __device__ float g_g[NN*CA];
static __device__ float g_o[NN*CA];
static __device__ float g_r1[NN*CA];
static __device__ __half g_qh[NN*CA];
static __device__ __half g_kh[NN*CA];
static __device__ __half g_vh[NN*CA];
static __device__ __half g_vt[CA*NN];
static __device__ __half g_po[(size_t)NSPLIT*NN*CA];
static __device__ float g_pm[NSPLIT*NN*NH];
static __device__ float g_pl[NSPLIT*NN*NH];
static __device__ uint8_t g_bias8[(size_t)NH*NN*NN];    // fp8 e4m3, 37.7 MB
static __device__ float g_u[NH*CZ];
static __device__ float g_su[NH];
static __device__ float g_cbp[NH];

__device__ __forceinline__ float sigmoidf_(float x) { return 1.f / (1.f + __expf(-x)); }
__device__ __forceinline__ float ex2_(float x) {
    float r; asm("ex2.approx.f32 %0, %1;" : "=f"(r) : "f"(x)); return r;
}

// ---------------- packed f32x2 helpers ----------------
__device__ __forceinline__ u64 pk2(float lo, float hi) {
    u64 r; asm("mov.b64 %0, {%1, %2};" : "=l"(r) : "f"(lo), "f"(hi)); return r;
}
__device__ __forceinline__ void upk2(u64 v, float& lo, float& hi) {
    asm("mov.b64 {%0, %1}, %2;" : "=f"(lo), "=f"(hi) : "l"(v));
}
__device__ __forceinline__ u64 f2fma(u64 a, u64 b, u64 c) {
    u64 d; asm("fma.rn.f32x2 %0, %1, %2, %3;" : "=l"(d) : "l"(a), "l"(b), "l"(c)); return d;
}
// 16B weight load directly into two packed-f32x2 operands (zero MOVs)
__device__ __forceinline__ void ldg2x64(const float* p, u64& a, u64& b) {
    asm("ld.global.nc.v2.u64 {%0, %1}, [%2];" : "=l"(a), "=l"(b) : "l"(p));
}

// ---------------- fp8 helpers ----------------
__device__ __forceinline__ uint8_t f2e4m3(float x) {
    uint16_t r;
    asm("cvt.rn.satfinite.e4m3x2.f32 %0, %1, %2;" : "=h"(r) : "f"(0.f), "f"(x));
    return (uint8_t)r;
}
__device__ __forceinline__ uint32_t e4m3x2_to_h2(uint32_t p) {
    uint32_t r;
    asm("cvt.rn.f16x2.e4m3x2 %0, %1;" : "=r"(r) : "h"((uint16_t)p));
    return r;
}
__device__ __forceinline__ uint32_t lds16(uint32_t addr) {
    uint16_t v; asm volatile("ld.shared.u16 %0, [%1];" : "=h"(v) : "r"(addr));
    return (uint32_t)v;
}

// ---------------- fp16 mma ----------------
__device__ __forceinline__ void mmaf16(float* c, const uint32_t* a, uint32_t b0, uint32_t b1) {
    asm volatile(
        "mma.sync.aligned.m16n8k16.row.col.f32.f16.f16.f32 "
        "{%0,%1,%2,%3}, {%4,%5,%6,%7}, {%8,%9}, {%0,%1,%2,%3};"
        : "+f"(c[0]), "+f"(c[1]), "+f"(c[2]), "+f"(c[3])
        : "r"(a[0]), "r"(a[1]), "r"(a[2]), "r"(a[3]), "r"(b0), "r"(b1));
}
__device__ __forceinline__ uint32_t lds32(uint32_t addr) {
    uint32_t v; asm volatile("ld.shared.b32 %0, [%1];" : "=r"(v) : "r"(addr)); return v;
}
__device__ __forceinline__ void sts32(uint32_t addr, uint32_t v) {
    asm volatile("st.shared.b32 [%0], %1;" :: "r"(addr), "r"(v));
}
__device__ __forceinline__ void cpa16(void* dst_smem, const void* src) {
    uint32_t d = (uint32_t)__cvta_generic_to_shared(dst_smem);
    asm volatile("cp.async.ca.shared.global [%0], [%1], 16;\n" :: "r"(d), "l"(src));
}
#define CPA_COMMIT() asm volatile("cp.async.commit_group;\n" ::: "memory")
#define CPA_WAIT2()  asm volatile("cp.async.wait_group 2;\n" ::: "memory")

__device__ __forceinline__ float wredsum(float v) {
    #pragma unroll
    for (int o = 16; o > 0; o >>= 1) v += __shfl_xor_sync(0xffffffffu, v, o);
    return v;
}

// ---------------- prep ----------------
__global__ void prep_kernel(const float* __restrict__ lnzw,
                            const float* __restrict__ lnzb,
                            const float* __restrict__ wb) {
    int tid = threadIdx.x;  // 64
    if (tid < NH * CZ) {
        int h = tid >> 4, j = tid & 15;
        g_u[h * CZ + j] = lnzw[j] * wb[j * NH + h];
    }
    if (tid < NH) {
        float acc = 0.f;
        for (int j = 0; j < CZ; j++) acc += lnzw[j] * wb[j * NH + tid];
        g_su[tid] = acc;
    } else if (tid < 2 * NH) {
        int h = tid - NH;
        float acc = 0.f;
        for (int j = 0; j < CZ; j++) acc += lnzb[j] * wb[j * NH + h];
        g_cbp[h] = acc;
    }
}

// ---------------- bias: LN(z)@wb * log2e -> fp8 e4m3, coalesced ----------------
__global__ void __launch_bounds__(256)
bias_kernel(const float* __restrict__ z) {
    __shared__ float u_sh[NH * CZ], su_sh[NH], cbp_sh[NH];
    __shared__ uint8_t stage[32 * 40];
    int tid = threadIdx.x;
    if (tid < NH * CZ) u_sh[tid] = g_u[tid];
    if (tid < NH) su_sh[tid] = g_su[tid];
    else if (tid < 2 * NH) cbp_sh[tid - NH] = g_cbp[tid - NH];
    __syncthreads();

    int q0 = blockIdx.x * 8, k0 = blockIdx.y * 32;
    int qq = tid >> 5, kk = tid & 31;
    const float* zp = z + ((size_t)(q0 + qq) * NN + (k0 + kk)) * CZ;
    float zv[16];
    *(float4*)&zv[0]  = *(const float4*)&zp[0];
    *(float4*)&zv[4]  = *(const float4*)&zp[4];
    *(float4*)&zv[8]  = *(const float4*)&zp[8];
    *(float4*)&zv[12] = *(const float4*)&zp[12];
    float sum = 0.f, zz = 0.f;
    #pragma unroll
    for (int j = 0; j < 16; j++) { sum += zv[j]; zz = fmaf(zv[j], zv[j], zz); }
    float mean = sum * (1.f / 16.f);
    float var = fmaf(-mean, mean, zz * (1.f / 16.f));
    float rs = rsqrtf(var + LNEPS);
    float rm = rs * mean;
    #pragma unroll
    for (int h = 0; h < NH; h++) {
        float d = 0.f;
        #pragma unroll
        for (int j = 0; j < 16; j++) d = fmaf(zv[j], u_sh[h * CZ + j], d);
        float b = fmaf(rs, d, fmaf(-rm, su_sh[h], cbp_sh[h])) * LOG2E;
        stage[(h * 8 + qq) * 40 + kk] = f2e4m3(b);
    }
    __syncthreads();
    if (tid < 128) {
        int row = tid >> 2, part = tid & 3;
        int hh = row >> 3, q = row & 7;
        uint2 v = *(uint2*)&stage[row * 40 + part * 8];
        *(uint2*)&g_bias8[((size_t)hh * NN + (q0 + q)) * NN + k0 + part * 8] = v;
    }
}

// ---------------- AdaLN1: fused LN(a), LN(s), matvec; 8 rows, 256 thr ----------------
__global__ void adaln1_kernel(const float* __restrict__ a,
                              const float* __restrict__ s,
                              const float* __restrict__ s_w,
                              const float* __restrict__ scale_w,
                              const float* __restrict__ shift_w,
                              const float* __restrict__ scale_b) {
    __shared__ float an_sh[8 * CA];
    __shared__ float sn_sh[8 * CS];
    int r0 = blockIdx.x * 8;
    int tid = threadIdx.x;
    int warp = tid >> 5, lane = tid & 31;
    {
        float4 va = ((const float4*)a)[(size_t)(r0 + warp) * 32 + lane];
        float sum = va.x + va.y + va.z + va.w;
        float ss = fmaf(va.x, va.x, fmaf(va.y, va.y, fmaf(va.z, va.z, va.w * va.w)));
        sum = wredsum(sum); ss = wredsum(ss);
        float mean = sum * (1.f / CA);
        float var = fmaf(-mean, mean, ss * (1.f / CA));
        float rs = rsqrtf(var + LNEPS);
        float4 o;
        o.x = (va.x - mean) * rs; o.y = (va.y - mean) * rs;
        o.z = (va.z - mean) * rs; o.w = (va.w - mean) * rs;
        *(float4*)&an_sh[warp * CA + lane * 4] = o;
    }
    {
        const float4* srow = (const float4*)(s + (size_t)(r0 + warp) * CS);
        float4 vs[3];
        float sum = 0.f, ss = 0.f;
        #pragma unroll
        for (int i = 0; i < 3; i++) {
            vs[i] = srow[i * 32 + lane];
            sum += vs[i].x + vs[i].y + vs[i].z + vs[i].w;
            ss = fmaf(vs[i].x, vs[i].x, fmaf(vs[i].y, vs[i].y,
                 fmaf(vs[i].z, vs[i].z, fmaf(vs[i].w, vs[i].w, ss))));
        }
        sum = wredsum(sum); ss = wredsum(ss);
        float mean = sum * (1.f / CS);
        float var = fmaf(-mean, mean, ss * (1.f / CS));
        float rs = rsqrtf(var + LNEPS);
        #pragma unroll
        for (int i = 0; i < 3; i++) {
            float4 nf;
            nf.x = (vs[i].x - mean) * rs; nf.y = (vs[i].y - mean) * rs;
            nf.z = (vs[i].z - mean) * rs; nf.w = (vs[i].w - mean) * rs;
            ((float4*)g_sn)[(size_t)(r0 + warp) * 96 + i * 32 + lane] = nf;
            float4 sw = ((const float4*)s_w)[i * 32 + lane];
            float4 f;
            f.x = nf.x * sw.x; f.y = nf.y * sw.y; f.z = nf.z * sw.z; f.w = nf.w * sw.w;
            *(float4*)&sn_sh[warp * CS + (i * 32 + lane) * 4] = f;
        }
    }
    __syncthreads();
    // matvec: thread = (channel quad q, row)
    int q = tid & 31, row = tid >> 5;
    u64 a1[2] = {0, 0}, a2[2] = {0, 0};
    #pragma unroll 4
    for (int j = 0; j < CS; j++) {
        u64 w1l, w1h, w2l, w2h;
        ldg2x64(scale_w + j * CA + 4 * q, w1l, w1h);
        ldg2x64(shift_w + j * CA + 4 * q, w2l, w2h);
        float sv = sn_sh[row * CS + j];
        u64 sp = pk2(sv, sv);
        a1[0] = f2fma(sp, w1l, a1[0]);
        a1[1] = f2fma(sp, w1h, a1[1]);
        a2[0] = f2fma(sp, w2l, a2[0]);
        a2[1] = f2fma(sp, w2h, a2[1]);
    }
    float4 sb = ((const float4*)scale_b)[q];
    float x0, x1, x2, x3, y0, y1, y2, y3;
    upk2(a1[0], x0, x1); upk2(a1[1], x2, x3);
    upk2(a2[0], y0, y1); upk2(a2[1], y2, y3);
    float4 an = *(float4*)&an_sh[row * CA + 4 * q];
    float4 o;
    o.x = sigmoidf_(x0 + sb.x) * an.x + y0;
    o.y = sigmoidf_(x1 + sb.y) * an.y + y1;
    o.z = sigmoidf_(x2 + sb.z) * an.z + y2;
    o.w = sigmoidf_(x3 + sb.w) * an.w + y3;
    ((float4*)g_h)[(size_t)(r0 + row) * 32 + q] = o;
}

// ---------------- QKVG: 8 rows, 256 thr, fp16 outputs ----------------
__global__ void qkvg_kernel(const float* __restrict__ wq, const float* __restrict__ bq,
                            const float* __restrict__ wk, const float* __restrict__ wv,
                            const float* __restrict__ wg) {
    __shared__ float h_sh[8 * CA];
    int r0 = blockIdx.x * 8;
    int tid = threadIdx.x;
    #pragma unroll
    for (int i = 0; i < 4; i++) {
        int idx = tid + i * 256;
        h_sh[idx] = g_h[(size_t)r0 * CA + idx];
    }
    __syncthreads();
    int q = tid & 31, row = tid >> 5;
    const float* wA = (blockIdx.y == 0) ? wq : wk;
    const float* wB = (blockIdx.y == 0) ? wg : wv;
    u64 aA[2] = {0, 0}, aB[2] = {0, 0};
    #pragma unroll 8
    for (int j = 0; j < CA; j++) {
        u64 w1l, w1h, w2l, w2h;
        ldg2x64(wA + j * CA + 4 * q, w1l, w1h);
        ldg2x64(wB + j * CA + 4 * q, w2l, w2h);
        float hv = h_sh[row * CA + j];
        u64 sp = pk2(hv, hv);
        aA[0] = f2fma(sp, w1l, aA[0]);
        aA[1] = f2fma(sp, w1h, aA[1]);
        aB[0] = f2fma(sp, w2l, aB[0]);
        aB[1] = f2fma(sp, w2h, aB[1]);
    }
    float x0, x1, x2, x3, y0, y1, y2, y3;
    upk2(aA[0], x0, x1); upk2(aA[1], x2, x3);
    upk2(aB[0], y0, y1); upk2(aB[1], y2, y3);
    int grow = r0 + row;
    if (blockIdx.y == 0) {
        const float qscale = 0.17677669529663687f * LOG2E;
        float4 b = ((const float4*)bq)[q];
        __half2 q01 = __floats2half2_rn((x0 + b.x) * qscale, (x1 + b.y) * qscale);
        __half2 q23 = __floats2half2_rn((x2 + b.z) * qscale, (x3 + b.w) * qscale);
        uint2 qp; qp.x = *(uint32_t*)&q01; qp.y = *(uint32_t*)&q23;
        ((uint2*)g_qh)[(size_t)grow * 32 + q] = qp;
        float4 g;
        g.x = sigmoidf_(y0); g.y = sigmoidf_(y1);
        g.z = sigmoidf_(y2); g.w = sigmoidf_(y3);
        ((float4*)g_g)[(size_t)grow * 32 + q] = g;
    } else {
        __half2 k01 = __floats2half2_rn(x0, x1);
        __half2 k23 = __floats2half2_rn(x2, x3);
        __half2 v01 = __floats2half2_rn(y0, y1);
        __half2 v23 = __floats2half2_rn(y2, y3);
        uint2 kp; kp.x = *(uint32_t*)&k01; kp.y = *(uint32_t*)&k23;
        uint2 vp; vp.x = *(uint32_t*)&v01; vp.y = *(uint32_t*)&v23;
        ((uint2*)g_kh)[(size_t)grow * 32 + q] = kp;
        ((uint2*)g_vh)[(size_t)grow * 32 + q] = vp;
    }
}

// ---------------- V transpose ----------------
__global__ void vt_kernel() {
    __shared__ __half vsh[32 * KSTRH];
    int tid = threadIdx.x;  // 256
    int t0 = blockIdx.x * 32;
    #pragma unroll
    for (int i = 0; i < 2; i++) {
        int c = tid + i * 256;
        int row = c >> 4, part = c & 15;
        *(uint4*)&vsh[row * KSTRH + part * 8] =
            *(const uint4*)&g_vh[(size_t)(t0 + row) * CA + part * 8];
    }
    __syncthreads();
    #pragma unroll
    for (int i = 0; i < 2; i++) {
        int c = tid + i * 256;
        int ch = c & 127, grp = c >> 7;
        __half tmp[8];
        #pragma unroll
        for (int j = 0; j < 8; j++) tmp[j] = vsh[(grp * 8 + j) * KSTRH + ch];
        *(uint4*)&g_vt[(size_t)ch * NN + t0 + grp * 8] = *(uint4*)tmp;
    }
}

// ---------------- Attention: fp16 mma, split-K, 4-stage pipeline, fp8 bias ----------------
__global__ void __launch_bounds__(ATHREADS, 2)
attn_kernel() {
    extern __shared__ __half smh[];
    __half* k_sh = smh;                                // NSTG*32*KSTRH halves
    __half* vt_sh = k_sh + NSTG * 32 * KSTRH;          // NSTG*128*VSTRH halves
    __half* p_sh = vt_sh + NSTG * 128 * VSTRH;         // 8*16*PSTRH halves (Q overlay)
    uint8_t* b8_sh = (uint8_t*)(p_sh + 8 * 16 * PSTRH); // NSTG*128*BSTR8 bytes

    int tid = threadIdx.x;
    int q0 = blockIdx.x * TQ;
    int kbase = blockIdx.y * KPS;

    auto issue_tile = [&](int k0, int buf) {
        #pragma unroll
        for (int i = 0; i < 2; i++) {
            int c = tid + i * 256;
            { int row = c >> 4, part = c & 15;
              cpa16(&k_sh[buf * 32 * KSTRH + row * KSTRH + part * 8],
                    &g_kh[(size_t)(k0 + row) * CA + part * 8]); }
            { int ch = c >> 2, part = c & 3;
              cpa16(&vt_sh[buf * 128 * VSTRH + ch * VSTRH + part * 8],
                    &g_vt[(size_t)ch * NN + k0 + part * 8]); }
        }
        { int row = tid >> 1, part = tid & 1;
          int hh = row >> 5, qq = row & 31;
          cpa16(&b8_sh[buf * 128 * BSTR8 + row * BSTR8 + part * 16],
                &g_bias8[((size_t)hh * NN + (q0 + qq)) * NN + k0 + part * 16]); }
    };

    // prologue: tiles 0,1,2 in flight
    issue_tile(kbase, 0);            CPA_COMMIT();
    issue_tile(kbase + TK, 1);       CPA_COMMIT();
    issue_tile(kbase + 2 * TK, 2);   CPA_COMMIT();

    // stage Q into p overlay
    #pragma unroll
    for (int i = 0; i < 2; i++) {
        int c = tid + i * 256;
        int row = c >> 4, part = c & 15;
        *(uint4*)&p_sh[row * KSTRH + part * 8] =
            *(const uint4*)&g_qh[(size_t)(q0 + row) * CA + part * 8];
    }
    __syncthreads();

    int warp = tid >> 5, lane = tid & 31;
    int h = warp & 3;
    int qg = warp >> 2;
    int g = lane >> 2;
    int t4 = lane & 3;
    int rowg = qg * 16 + g;

    uint32_t pB = (uint32_t)__cvta_generic_to_shared(p_sh);
    uint32_t kB = (uint32_t)__cvta_generic_to_shared(k_sh);
    uint32_t vB = (uint32_t)__cvta_generic_to_shared(vt_sh);
    uint32_t bB = (uint32_t)__cvta_generic_to_shared(b8_sh);

    uint32_t qa[2][4];
    #pragma unroll
    for (int dc = 0; dc < 2; dc++) {
        uint32_t base  = pB + ((rowg)     * KSTRH + h * 32 + dc * 16 + 2 * t4) * 2;
        uint32_t base8 = pB + ((rowg + 8) * KSTRH + h * 32 + dc * 16 + 2 * t4) * 2;
        qa[dc][0] = lds32(base);
        qa[dc][1] = lds32(base8);
        qa[dc][2] = lds32(base + 16);
        qa[dc][3] = lds32(base8 + 16);
    }
    __syncthreads();   // overlay becomes p_sh

    uint32_t pw = pB + warp * 16 * PSTRH * 2;

    float m0 = -1e30f, m1 = -1e30f, l0 = 0.f, l1 = 0.f;
    float o[4][4];
    #pragma unroll
    for (int nb = 0; nb < 4; nb++)
        #pragma unroll
        for (int i = 0; i < 4; i++) o[nb][i] = 0.f;

    for (int t = 0; t < NT; t++) {
        CPA_WAIT2();            // group t complete
        __syncthreads();

        if (t + 3 < NT) issue_tile(kbase + (t + 3) * TK, (t + 3) % NSTG);
        CPA_COMMIT();           // uniform group accounting

        int bi = t % NSTG;
        uint32_t kbuf = kB + bi * 32 * KSTRH * 2;
        uint32_t vbuf = vB + bi * 128 * VSTRH * 2;
        uint32_t bbuf = bB + bi * 128 * BSTR8;

        // QK^T mma with fp8 bias-initialized C (base-2 domain)
        float c[4][4];
        #pragma unroll
        for (int kb = 0; kb < 4; kb++) {
            uint32_t p01 = e4m3x2_to_h2(lds16(bbuf + (h * 32 + rowg)     * BSTR8 + kb * 8 + 2 * t4));
            uint32_t p23 = e4m3x2_to_h2(lds16(bbuf + (h * 32 + rowg + 8) * BSTR8 + kb * 8 + 2 * t4));
            float2 f01 = __half22float2(*(__half2*)&p01);
            float2 f23 = __half22float2(*(__half2*)&p23);
            c[kb][0] = f01.x; c[kb][1] = f01.y;
            c[kb][2] = f23.x; c[kb][3] = f23.y;
        }
        #pragma unroll
        for (int dc = 0; dc < 2; dc++) {
            #pragma unroll
            for (int kb = 0; kb < 4; kb++) {
                uint32_t base = kbuf + ((kb * 8 + g) * KSTRH + h * 32 + dc * 16 + 2 * t4) * 2;
                uint32_t b0 = lds32(base);
                uint32_t b1 = lds32(base + 16);
                mmaf16(c[kb], qa[dc], b0, b1);
            }
        }

        // online softmax (base-2)
        float v0[8] = {c[0][0], c[0][1], c[1][0], c[1][1], c[2][0], c[2][1], c[3][0], c[3][1]};
        float v1[8] = {c[0][2], c[0][3], c[1][2], c[1][3], c[2][2], c[2][3], c[3][2], c[3][3]};
        float mx0 = v0[0], mx1 = v1[0];
        #pragma unroll
        for (int i = 1; i < 8; i++) { mx0 = fmaxf(mx0, v0[i]); mx1 = fmaxf(mx1, v1[i]); }
        mx0 = fmaxf(mx0, __shfl_xor_sync(0xffffffffu, mx0, 1));
        mx0 = fmaxf(mx0, __shfl_xor_sync(0xffffffffu, mx0, 2));
        mx1 = fmaxf(mx1, __shfl_xor_sync(0xffffffffu, mx1, 1));
        mx1 = fmaxf(mx1, __shfl_xor_sync(0xffffffffu, mx1, 2));
        float mn0 = fmaxf(m0, mx0), mn1 = fmaxf(m1, mx1);
        float sum0 = 0.f, sum1 = 0.f;
        #pragma unroll
        for (int i = 0; i < 8; i++) {
            v0[i] = ex2_(v0[i] - mn0); sum0 += v0[i];
            v1[i] = ex2_(v1[i] - mn1); sum1 += v1[i];
        }
        sum0 += __shfl_xor_sync(0xffffffffu, sum0, 1);
        sum0 += __shfl_xor_sync(0xffffffffu, sum0, 2);
        sum1 += __shfl_xor_sync(0xffffffffu, sum1, 1);
        sum1 += __shfl_xor_sync(0xffffffffu, sum1, 2);
        float scl0 = ex2_(m0 - mn0), scl1 = ex2_(m1 - mn1);
        l0 = l0 * scl0 + sum0; m0 = mn0;
        l1 = l1 * scl1 + sum1; m1 = mn1;

        // store P (fp16)
        #pragma unroll
        for (int kb = 0; kb < 4; kb++) {
            __half2 h0 = __floats2half2_rn(v0[2 * kb], v0[2 * kb + 1]);
            __half2 h1 = __floats2half2_rn(v1[2 * kb], v1[2 * kb + 1]);
            sts32(pw + ((g)     * PSTRH + kb * 8 + 2 * t4) * 2, *(uint32_t*)&h0);
            sts32(pw + ((g + 8) * PSTRH + kb * 8 + 2 * t4) * 2, *(uint32_t*)&h1);
        }
        __syncwarp();

        // rescale O
        #pragma unroll
        for (int nb = 0; nb < 4; nb++) {
            o[nb][0] *= scl0; o[nb][1] *= scl0;
            o[nb][2] *= scl1; o[nb][3] *= scl1;
        }

        // P @ V
        #pragma unroll
        for (int kc = 0; kc < 2; kc++) {
            uint32_t pa[4];
            pa[0] = lds32(pw + ((g)     * PSTRH + kc * 16 + 2 * t4) * 2);
            pa[1] = lds32(pw + ((g + 8) * PSTRH + kc * 16 + 2 * t4) * 2);
            pa[2] = lds32(pw + ((g)     * PSTRH + kc * 16 + 2 * t4 + 8) * 2);
            pa[3] = lds32(pw + ((g + 8) * PSTRH + kc * 16 + 2 * t4 + 8) * 2);
            #pragma unroll
            for (int nb = 0; nb < 4; nb++) {
                uint32_t vb = vbuf + ((h * 32 + nb * 8 + g) * VSTRH + kc * 16 + 2 * t4) * 2;
                uint32_t b0 = lds32(vb);
                uint32_t b1 = lds32(vb + 16);
                mmaf16(o[nb], pa, b0, b1);
            }
        }
        __syncwarp();
    }

    // epilogue
    size_t sp = blockIdx.y;
    float il0 = 1.f / l0, il1 = 1.f / l1;
    __half2* poh = (__half2*)g_po;
    #pragma unroll
    for (int nb = 0; nb < 4; nb++) {
        int q_a = q0 + rowg, q_b = q0 + rowg + 8;
        poh[(sp * NN + q_a) * 64 + h * 16 + nb * 4 + t4] =
            __floats2half2_rn(o[nb][0] * il0, o[nb][1] * il0);
        poh[(sp * NN + q_b) * 64 + h * 16 + nb * 4 + t4] =
            __floats2half2_rn(o[nb][2] * il1, o[nb][3] * il1);
    }
    if (t4 == 0) {
        int q_a = q0 + rowg, q_b = q0 + rowg + 8;
        g_pm[(sp * NN + q_a) * NH + h] = m0;
        g_pl[(sp * NN + q_a) * NH + h] = l0;
        g_pm[(sp * NN + q_b) * NH + h] = m1;
        g_pl[(sp * NN + q_b) * NH + h] = l1;
    }
}

// ---------------- split-K combine ----------------
__global__ void combine_kernel() {
    int tid = threadIdx.x;               // 256
    int q = blockIdx.x * 2 + (tid >> 7);
    int hd = tid & 127;
    int h = hd >> 5;
    float ms[NSPLIT];
    float M = -1e30f;
    #pragma unroll
    for (int s = 0; s < NSPLIT; s++) {
        ms[s] = g_pm[((size_t)s * NN + q) * NH + h];
        M = fmaxf(M, ms[s]);
    }
    float osum = 0.f, lsum = 0.f;
    #pragma unroll
    for (int s = 0; s < NSPLIT; s++) {
        float w = ex2_(ms[s] - M);
        float lw = g_pl[((size_t)s * NN + q) * NH + h];
        lsum = fmaf(w, lw, lsum);
        osum = fmaf(w * lw, __half2float(g_po[((size_t)s * NN + q) * CA + hd]), osum);
    }
    g_o[(size_t)q * CA + hd] = osum / lsum;
}

// ---------------- fused: out proj + gate + residual1 + LN + AdaLN2; 8 rows, 256 thr ----------------
__global__ void post_kernel(const float* __restrict__ wo,
                            const float* __restrict__ s,
                            const float* __restrict__ sg1w,
                            const float* __restrict__ sg1b,
                            const float* __restrict__ a,
                            const float* __restrict__ a2sw,
                            const float* __restrict__ a2scw,
                            const float* __restrict__ a2shw,
                            const float* __restrict__ a2scb) {
    __shared__ float go_sh[8 * CA];    // later an2
    __shared__ float s_sh[8 * CS];     // raw s, later sn2
    __shared__ float r1_sh[8 * CA];
    int r0 = blockIdx.x * 8;
    int tid = threadIdx.x;
    int warp = tid >> 5, lane = tid & 31;
    int q = tid & 31, row = tid >> 5;

    #pragma unroll
    for (int i = 0; i < 4; i++) {
        int idx = tid + i * 256;
        go_sh[idx] = g_g[(size_t)r0 * CA + idx] * g_o[(size_t)r0 * CA + idx];
    }
    #pragma unroll
    for (int i = 0; i < 12; i++) {
        int idx = tid + i * 256;
        s_sh[idx] = s[(size_t)r0 * CS + idx];
    }
    __syncthreads();

    // matvec 1
    {
        u64 aA[2] = {0, 0};
        #pragma unroll 8
        for (int j = 0; j < CA; j++) {
            u64 wl, wh;
            ldg2x64(wo + j * CA + 4 * q, wl, wh);
            float gv = go_sh[row * CA + j];
            u64 sp = pk2(gv, gv);
            aA[0] = f2fma(sp, wl, aA[0]);
            aA[1] = f2fma(sp, wh, aA[1]);
        }
        u64 aG[2] = {0, 0};
        #pragma unroll 4
        for (int j = 0; j < CS; j++) {
            u64 wl, wh;
            ldg2x64(sg1w + j * CA + 4 * q, wl, wh);
            float sv = s_sh[row * CS + j];
            u64 sp = pk2(sv, sv);
            aG[0] = f2fma(sp, wl, aG[0]);
            aG[1] = f2fma(sp, wh, aG[1]);
        }
        float4 gb = ((const float4*)sg1b)[q];
        float x0, x1, x2, x3, y0, y1, y2, y3;
        upk2(aA[0], x0, x1); upk2(aA[1], x2, x3);
        upk2(aG[0], y0, y1); upk2(aG[1], y2, y3);
        float4 av = ((const float4*)a)[(size_t)(r0 + row) * 32 + q];
        float4 o;
        o.x = sigmoidf_(y0 + gb.x) * x0 + av.x;
        o.y = sigmoidf_(y1 + gb.y) * x1 + av.y;
        o.z = sigmoidf_(y2 + gb.z) * x2 + av.z;
        o.w = sigmoidf_(y3 + gb.w) * x3 + av.w;
        ((float4*)g_r1)[(size_t)(r0 + row) * 32 + q] = o;
        *(float4*)&r1_sh[row * CA + 4 * q] = o;
    }
    __syncthreads();

    // LN(r1): warp per row -> go_sh (an2)
    {
        float4 va = *(float4*)&r1_sh[warp * CA + lane * 4];
        float sum = va.x + va.y + va.z + va.w;
        float ss = fmaf(va.x, va.x, fmaf(va.y, va.y, fmaf(va.z, va.z, va.w * va.w)));
        sum = wredsum(sum); ss = wredsum(ss);
        float mean = sum * (1.f / CA);
        float var = fmaf(-mean, mean, ss * (1.f / CA));
        float rs = rsqrtf(var + LNEPS);
        float4 o;
        o.x = (va.x - mean) * rs; o.y = (va.y - mean) * rs;
        o.z = (va.z - mean) * rs; o.w = (va.w - mean) * rs;
        *(float4*)&go_sh[warp * CA + lane * 4] = o;
    }
    #pragma unroll
    for (int i = 0; i < 12; i++) {
        int idx = tid + i * 256;
        s_sh[idx] = g_sn[(size_t)r0 * CS + idx] * a2sw[idx % CS];
    }
    __syncthreads();

    // matvec 2: AdaLN2
    {
        u64 a1[2] = {0, 0}, a2[2] = {0, 0};
        #pragma unroll 4
        for (int j = 0; j < CS; j++) {
            u64 w1l, w1h, w2l, w2h;
            ldg2x64(a2scw + j * CA + 4 * q, w1l, w1h);
            ldg2x64(a2shw + j * CA + 4 * q, w2l, w2h);
            float sv = s_sh[row * CS + j];
            u64 sp = pk2(sv, sv);
            a1[0] = f2fma(sp, w1l, a1[0]);
            a1[1] = f2fma(sp, w1h, a1[1]);
            a2[0] = f2fma(sp, w2l, a2[0]);
            a2[1] = f2fma(sp, w2h, a2[1]);
        }
        float4 sb = ((const float4*)a2scb)[q];
        float x0, x1, x2, x3, y0, y1, y2, y3;
        upk2(a1[0], x0, x1); upk2(a1[1], x2, x3);
        upk2(a2[0], y0, y1); upk2(a2[1], y2, y3);
        float4 an = *(float4*)&go_sh[row * CA + 4 * q];
        float4 o;
        o.x = sigmoidf_(x0 + sb.x) * an.x + y0;
        o.y = sigmoidf_(x1 + sb.y) * an.y + y1;
        o.z = sigmoidf_(x2 + sb.z) * an.z + y2;
        o.w = sigmoidf_(x3 + sb.w) * an.w + y3;
        ((float4*)g_h2)[(size_t)(r0 + row) * 32 + q] = o;
    }
}

// ---------------- SwiGLU FFN + gate + residual 2; 8 rows, 256 thr ----------------
__global__ void ffn_kernel(const float* __restrict__ w1, const float* __restrict__ w2,
                           const float* __restrict__ wout,
                           const float* __restrict__ s,
                           const float* __restrict__ sg2w, const float* __restrict__ sg2b,
                           float* __restrict__ out) {
    __shared__ float h_sh[8 * CA];
    __shared__ float s_sh[8 * CS];
    __shared__ __align__(16) float gt_sh[8 * CF];
    int r0 = blockIdx.x * 8;
    int tid = threadIdx.x;   // 256
    #pragma unroll
    for (int i = 0; i < 4; i++) {
        int idx = tid + i * 256;
        h_sh[idx] = g_h2[(size_t)r0 * CA + idx];
    }
    #pragma unroll
    for (int i = 0; i < 12; i++) {
        int idx = tid + i * 256;
        s_sh[idx] = s[(size_t)r0 * CS + idx];
    }
    __syncthreads();
    {
        int quad = tid & 63, rg = tid >> 6;   // rows 2rg, 2rg+1
        u64 u1[2][2] = {{0, 0}, {0, 0}}, u2[2][2] = {{0, 0}, {0, 0}};
        #pragma unroll 4
        for (int j = 0; j < CA; j++) {
            u64 w1l, w1h, w2l, w2h;
            ldg2x64(w1 + j * CF + 4 * quad, w1l, w1h);
            ldg2x64(w2 + j * CF + 4 * quad, w2l, w2h);
            float h0 = h_sh[(2 * rg + 0) * CA + j];
            float h1 = h_sh[(2 * rg + 1) * CA + j];
            u64 s0 = pk2(h0, h0), s1 = pk2(h1, h1);
            u1[0][0] = f2fma(s0, w1l, u1[0][0]);
            u1[0][1] = f2fma(s0, w1h, u1[0][1]);
            u1[1][0] = f2fma(s1, w1l, u1[1][0]);
            u1[1][1] = f2fma(s1, w1h, u1[1][1]);
            u2[0][0] = f2fma(s0, w2l, u2[0][0]);
            u2[0][1] = f2fma(s0, w2h, u2[0][1]);
            u2[1][0] = f2fma(s1, w2l, u2[1][0]);
            u2[1][1] = f2fma(s1, w2h, u2[1][1]);
        }
        #pragma unroll
        for (int rr = 0; rr < 2; rr++) {
            float x0, x1, x2, x3, y0, y1, y2, y3;
            upk2(u1[rr][0], x0, x1); upk2(u1[rr][1], x2, x3);
            upk2(u2[rr][0], y0, y1); upk2(u2[rr][1], y2, y3);
            float4 gv;
            gv.x = (x0 * sigmoidf_(x0)) * y0;
            gv.y = (x1 * sigmoidf_(x1)) * y1;
            gv.z = (x2 * sigmoidf_(x2)) * y2;
            gv.w = (x3 * sigmoidf_(x3)) * y3;
            *(float4*)&gt_sh[(2 * rg + rr) * CF + 4 * quad] = gv;
        }
    }
    __syncthreads();
    {
        int q = tid & 31, row = tid >> 5;
        u64 aF[2] = {0, 0}, aG[2] = {0, 0};
        #pragma unroll 8
        for (int j = 0; j < CF; j++) {
            u64 wl, wh;
            ldg2x64(wout + j * CA + 4 * q, wl, wh);
            float gv = gt_sh[row * CF + j];
            u64 sp = pk2(gv, gv);
            aF[0] = f2fma(sp, wl, aF[0]);
            aF[1] = f2fma(sp, wh, aF[1]);
        }
        #pragma unroll 4
        for (int j = 0; j < CS; j++) {
            u64 wl, wh;
            ldg2x64(sg2w + j * CA + 4 * q, wl, wh);
            float sv = s_sh[row * CS + j];
            u64 sp = pk2(sv, sv);
            aG[0] = f2fma(sp, wl, aG[0]);
            aG[1] = f2fma(sp, wh, aG[1]);
        }
        float4 gb = ((const float4*)sg2b)[q];
        float f0, f1, f2, f3, g0, g1, g2, g3;
        upk2(aF[0], f0, f1); upk2(aF[1], f2, f3);
        upk2(aG[0], g0, g1); upk2(aG[1], g2, g3);
        float4 rv = ((const float4*)g_r1)[(size_t)(r0 + row) * 32 + q];
        float4 o;
        o.x = sigmoidf_(g0 + gb.x) * f0 + rv.x;
        o.y = sigmoidf_(g1 + gb.y) * f1 + rv.y;
        o.z = sigmoidf_(g2 + gb.z) * f2 + rv.z;
        o.w = sigmoidf_(g3 + gb.w) * f3 + rv.w;
        ((float4*)out)[(size_t)(r0 + row) * 32 + q] = o;
    }
}

// ---------------- launch ----------------
extern "C" void kernel_launch(void* const* d_in, const int* in_sizes, int n_in,
                              void* d_out, int out_size) {
    const float* a      = (const float*)d_in[0];
    const float* s      = (const float*)d_in[1];
    const float* z      = (const float*)d_in[2];
    const float* a1sw   = (const float*)d_in[3];
    const float* a1scw  = (const float*)d_in[4];
    const float* a1scb  = (const float*)d_in[5];
    const float* a1shw  = (const float*)d_in[6];
    const float* wq     = (const float*)d_in[7];
    const float* bq     = (const float*)d_in[8];
    const float* wk     = (const float*)d_in[9];
    const float* wv     = (const float*)d_in[10];
    const float* lnzw   = (const float*)d_in[11];
    const float* lnzb   = (const float*)d_in[12];
    const float* wb     = (const float*)d_in[13];
    const float* wg     = (const float*)d_in[14];
    const float* wo     = (const float*)d_in[15];
    const float* sg1w   = (const float*)d_in[16];
    const float* sg1b   = (const float*)d_in[17];
    const float* a2sw   = (const float*)d_in[18];
    const float* a2scw  = (const float*)d_in[19];
    const float* a2scb  = (const float*)d_in[20];
    const float* a2shw  = (const float*)d_in[21];
    const float* w1     = (const float*)d_in[22];
    const float* w2     = (const float*)d_in[23];
    const float* wout   = (const float*)d_in[24];
    const float* sg2w   = (const float*)d_in[25];
    const float* sg2b   = (const float*)d_in[26];
    float* out = (float*)d_out;

    const int ATTN_SMEM =
        (NSTG * 32 * KSTRH + NSTG * 128 * VSTRH + 8 * 16 * PSTRH) * 2 + NSTG * 128 * BSTR8;
    static int attrset = 0;
    if (!attrset) {
        cudaFuncSetAttribute(attn_kernel, cudaFuncAttributeMaxDynamicSharedMemorySize, ATTN_SMEM);
        attrset = 1;
    }

    prep_kernel<<<1, 64>>>(lnzw, lnzb, wb);
    bias_kernel<<<dim3(NN / 8, NN / 32), 256>>>(z);
    adaln1_kernel<<<NN / 8, 256>>>(a, s, a1sw, a1scw, a1shw, a1scb);
    qkvg_kernel<<<dim3(NN / 8, 2), 256>>>(wq, bq, wk, wv, wg);
    vt_kernel<<<NN / 32, 256>>>();
    attn_kernel<<<dim3(NN / TQ, NSPLIT), ATHREADS, ATTN_SMEM>>>();
    combine_kernel<<<NN / 2, 256>>>();
    post_kernel<<<NN / 8, 256>>>(wo, s, sg1w, sg1b, a, a2sw, a2scw, a2shw, a2scb);
    ffn_kernel<<<NN / 8, 256>>>(w1, w2, wout, s, sg2w, sg2b, out);
    (void)in_sizes; (void)n_in; (void)out_size;
}

// round 13
// speedup vs baseline: 1.2689x; 1.2689x over previous
#include <cuda_runtime.h>
#include <cuda_fp16.h>
#include <math.h>
#include <stdint.h>

typedef unsigned long long u64;

#define NN 3072
#define CA 128
#define CS 384
#define CZ 16
#define NH 4
#define DH 32
#define CF 256
#define LNEPS 1e-5f
#define LOG2E 1.4426950408889634f

#define TQ 32
#define TK 32
#define NSPLIT 6
#define KPS (NN / NSPLIT)     // 512
#define NT (KPS / TK)         // 16
#define NSTG 3
#define KSTRH 136
#define VSTRH 40
#define BSTRH 40
#define PSTRH 40
#define ATHREADS 256

// ---------------- scratch ----------------
static __device__ float g_sn[NN*CS];
static __device__ float g_h[NN*CA];
static __device__ float g_h2[NN*CA];
static __device__ float g_g[NN*CA];
static __device__ float g_o[NN*CA];
static __device__ float g_r1[NN*CA];
static __device__ __half g_qh[NN*CA];
static __device__ __half g_kh[NN*CA];
static __device__ __half g_vh[NN*CA];
static __device__ __half g_vt[CA*NN];
static __device__ __half g_po[(size_t)NSPLIT*NN*CA];
static __device__ float g_pm[NSPLIT*NN*NH];
static __device__ float g_pl[NSPLIT*NN*NH];
static __device__ __half g_bias[(size_t)NH*NN*NN];

__device__ __forceinline__ float sigmoidf_(float x) { return 1.f / (1.f + __expf(-x)); }
__device__ __forceinline__ float ex2_(float x) {
    float r; asm("ex2.approx.f32 %0, %1;" : "=f"(r) : "f"(x)); return r;
}

// ---------------- packed f32x2 helpers ----------------
__device__ __forceinline__ u64 pk2(float lo, float hi) {
    u64 r; asm("mov.b64 %0, {%1, %2};" : "=l"(r) : "f"(lo), "f"(hi)); return r;
}
__device__ __forceinline__ void upk2(u64 v, float& lo, float& hi) {
    asm("mov.b64 {%0, %1}, %2;" : "=f"(lo), "=f"(hi) : "l"(v));
}
__device__ __forceinline__ u64 f2fma(u64 a, u64 b, u64 c) {
    u64 d; asm("fma.rn.f32x2 %0, %1, %2, %3;" : "=l"(d) : "l"(a), "l"(b), "l"(c)); return d;
}
__device__ __forceinline__ u64 f2add(u64 a, u64 b) {
    u64 d; asm("add.rn.f32x2 %0, %1, %2;" : "=l"(d) : "l"(a), "l"(b)); return d;
}
__device__ __forceinline__ u64 f2mul(u64 a, u64 b) {
    u64 d; asm("mul.rn.f32x2 %0, %1, %2;" : "=l"(d) : "l"(a), "l"(b)); return d;
}
// 16B global load into two packed operands
__device__ __forceinline__ void ldg2x64(const float* p, u64& a, u64& b) {
    asm("ld.global.nc.v2.u64 {%0, %1}, [%2];" : "=l"(a), "=l"(b) : "l"(p));
}

// ---------------- fp16 mma ----------------
__device__ __forceinline__ void mmaf16(float* c, const uint32_t* a, uint32_t b0, uint32_t b1) {
    asm volatile(
        "mma.sync.aligned.m16n8k16.row.col.f32.f16.f16.f32 "
        "{%0,%1,%2,%3}, {%4,%5,%6,%7}, {%8,%9}, {%0,%1,%2,%3};"
        : "+f"(c[0]), "+f"(c[1]), "+f"(c[2]), "+f"(c[3])
        : "r"(a[0]), "r"(a[1]), "r"(a[2]), "r"(a[3]), "r"(b0), "r"(b1));
}
__device__ __forceinline__ uint32_t lds32(uint32_t addr) {
    uint32_t v; asm volatile("ld.shared.b32 %0, [%1];" : "=r"(v) : "r"(addr)); return v;
}
__device__ __forceinline__ void sts32(uint32_t addr, uint32_t v) {
    asm volatile("st.shared.b32 [%0], %1;" :: "r"(addr), "r"(v));
}
__device__ __forceinline__ void cpa16(void* dst_smem, const void* src) {
    uint32_t d = (uint32_t)__cvta_generic_to_shared(dst_smem);
    asm volatile("cp.async.ca.shared.global [%0], [%1], 16;\n" :: "r"(d), "l"(src));
}
#define CPA_COMMIT() asm volatile("cp.async.commit_group;\n" ::: "memory")
#define CPA_WAIT1()  asm volatile("cp.async.wait_group 1;\n" ::: "memory")

__device__ __forceinline__ float wredsum(float v) {
    #pragma unroll
    for (int o = 16; o > 0; o >>= 1) v += __shfl_xor_sync(0xffffffffu, v, o);
    return v;
}

// ---------------- bias: LN(z)@wb * log2e -> fp16, packed math, prep fused ----------------
__global__ void __launch_bounds__(256)
bias_kernel(const float* __restrict__ z,
            const float* __restrict__ lnzw,
            const float* __restrict__ lnzb,
            const float* __restrict__ wb) {
    __shared__ __align__(8) float u_sh[NH * CZ];
    __shared__ float su_sh[NH], cbp_sh[NH];
    __shared__ __half stage[32 * BSTRH];
    int tid = threadIdx.x;
    // fold constants (prep)
    if (tid < NH * CZ) {
        int h = tid >> 4, j = tid & 15;
        u_sh[h * CZ + j] = lnzw[j] * wb[j * NH + h];
    } else if (tid < NH * CZ + 2 * NH) {
        int r = tid - NH * CZ;
        int h = r & 3;
        float acc = 0.f;
        if (r < NH) { for (int j = 0; j < CZ; j++) acc += lnzw[j] * wb[j * NH + h]; su_sh[h] = acc; }
        else        { for (int j = 0; j < CZ; j++) acc += lnzb[j] * wb[j * NH + h]; cbp_sh[h] = acc; }
    }
    __syncthreads();

    int q0 = blockIdx.x * 8, k0 = blockIdx.y * 32;
    int qq = tid >> 5, kk = tid & 31;
    const float* zrow = z + ((size_t)(q0 + qq) * NN + (k0 + kk)) * CZ;
    u64 zp[8];
    ldg2x64(zrow + 0,  zp[0], zp[1]);
    ldg2x64(zrow + 4,  zp[2], zp[3]);
    ldg2x64(zrow + 8,  zp[4], zp[5]);
    ldg2x64(zrow + 12, zp[6], zp[7]);
    u64 s2 = f2add(f2add(zp[0], zp[1]), f2add(zp[2], zp[3]));
    s2 = f2add(s2, f2add(f2add(zp[4], zp[5]), f2add(zp[6], zp[7])));
    u64 zz2 = f2mul(zp[0], zp[0]);
    #pragma unroll
    for (int g = 1; g < 8; g++) zz2 = f2fma(zp[g], zp[g], zz2);
    float slo, shi, zlo, zhi;
    upk2(s2, slo, shi);
    upk2(zz2, zlo, zhi);
    float sum = slo + shi, zz = zlo + zhi;
    float mean = sum * (1.f / 16.f);
    float var = fmaf(-mean, mean, zz * (1.f / 16.f));
    float rs = rsqrtf(var + LNEPS);
    float rm = rs * mean;
    #pragma unroll
    for (int h = 0; h < NH; h++) {
        const u64* u2 = (const u64*)&u_sh[h * CZ];
        u64 d2 = f2mul(zp[0], u2[0]);
        #pragma unroll
        for (int g = 1; g < 8; g++) d2 = f2fma(zp[g], u2[g], d2);
        float dlo, dhi;
        upk2(d2, dlo, dhi);
        float b = fmaf(rs, dlo + dhi, fmaf(-rm, su_sh[h], cbp_sh[h])) * LOG2E;
        stage[(h * 8 + qq) * BSTRH + kk] = __float2half(b);
    }
    __syncthreads();
    if (tid < 128) {
        int row = tid >> 2, part = tid & 3;
        int hh = row >> 3, q = row & 7;
        uint4 v = *(uint4*)&stage[row * BSTRH + part * 8];
        *(uint4*)&g_bias[((size_t)hh * NN + (q0 + q)) * NN + k0 + part * 8] = v;
    }
}

// ---------------- AdaLN1: fused LN(a), LN(s), matvec; 8 rows, 256 thr ----------------
__global__ void adaln1_kernel(const float* __restrict__ a,
                              const float* __restrict__ s,
                              const float* __restrict__ s_w,
                              const float* __restrict__ scale_w,
                              const float* __restrict__ shift_w,
                              const float* __restrict__ scale_b) {
    __shared__ float an_sh[8 * CA];
    __shared__ float sn_sh[8 * CS];
    int r0 = blockIdx.x * 8;
    int tid = threadIdx.x;
    int warp = tid >> 5, lane = tid & 31;
    // LN(a): warp per row
    {
        float4 va = ((const float4*)a)[(size_t)(r0 + warp) * (CA / 4) + lane];
        float sum = va.x + va.y + va.z + va.w;
        float ss = fmaf(va.x, va.x, fmaf(va.y, va.y, fmaf(va.z, va.z, va.w * va.w)));
        sum = wredsum(sum); ss = wredsum(ss);
        float mean = sum * (1.f / CA);
        float var = fmaf(-mean, mean, ss * (1.f / CA));
        float rs = rsqrtf(var + LNEPS);
        float4 o;
        o.x = (va.x - mean) * rs; o.y = (va.y - mean) * rs;
        o.z = (va.z - mean) * rs; o.w = (va.w - mean) * rs;
        *(float4*)&an_sh[warp * CA + lane * 4] = o;
    }
    // LN(s): warp per row
    {
        const float4* srow = (const float4*)(s + (size_t)(r0 + warp) * CS);
        float4 vs[3];
        float sum = 0.f, ss = 0.f;
        #pragma unroll
        for (int i = 0; i < 3; i++) {
            vs[i] = srow[i * 32 + lane];
            sum += vs[i].x + vs[i].y + vs[i].z + vs[i].w;
            ss = fmaf(vs[i].x, vs[i].x, fmaf(vs[i].y, vs[i].y,
                 fmaf(vs[i].z, vs[i].z, fmaf(vs[i].w, vs[i].w, ss))));
        }
        sum = wredsum(sum); ss = wredsum(ss);
        float mean = sum * (1.f / CS);
        float var = fmaf(-mean, mean, ss * (1.f / CS));
        float rs = rsqrtf(var + LNEPS);
        #pragma unroll
        for (int i = 0; i < 3; i++) {
            float4 nf;
            nf.x = (vs[i].x - mean) * rs; nf.y = (vs[i].y - mean) * rs;
            nf.z = (vs[i].z - mean) * rs; nf.w = (vs[i].w - mean) * rs;
            ((float4*)g_sn)[(size_t)(r0 + warp) * (CS / 4) + i * 32 + lane] = nf;
            float4 sw = ((const float4*)s_w)[i * 32 + lane];
            float4 f;
            f.x = nf.x * sw.x; f.y = nf.y * sw.y; f.z = nf.z * sw.z; f.w = nf.w * sw.w;
            *(float4*)&sn_sh[warp * CS + (i * 32 + lane) * 4] = f;
        }
    }
    __syncthreads();
    int cp = tid & 63, rg = tid >> 6;  // rg 0..3 -> rows 2rg, 2rg+1
    const u64* sw2 = (const u64*)scale_w;
    const u64* hw2 = (const u64*)shift_w;
    u64 a1[2] = {0, 0}, a2[2] = {0, 0};
    #pragma unroll 4
    for (int j = 0; j < CS; j++) {
        u64 w1 = sw2[j * 64 + cp];
        u64 w2 = hw2[j * 64 + cp];
        float sv0 = sn_sh[(2 * rg + 0) * CS + j];
        float sv1 = sn_sh[(2 * rg + 1) * CS + j];
        u64 s0 = pk2(sv0, sv0), s1 = pk2(sv1, sv1);
        a1[0] = f2fma(s0, w1, a1[0]);
        a1[1] = f2fma(s1, w1, a1[1]);
        a2[0] = f2fma(s0, w2, a2[0]);
        a2[1] = f2fma(s1, w2, a2[1]);
    }
    float sb0 = scale_b[2 * cp], sb1 = scale_b[2 * cp + 1];
    #pragma unroll
    for (int rr = 0; rr < 2; rr++) {
        int row = r0 + 2 * rg + rr;
        float x0, x1, y0, y1;
        upk2(a1[rr], x0, x1);
        upk2(a2[rr], y0, y1);
        float2 anv = *(float2*)&an_sh[(2 * rg + rr) * CA + 2 * cp];
        float2 o;
        o.x = sigmoidf_(x0 + sb0) * anv.x + y0;
        o.y = sigmoidf_(x1 + sb1) * anv.y + y1;
        ((float2*)g_h)[(size_t)row * 64 + cp] = o;
    }
}

// ---------------- QKVG: 8 rows, 256 thr, fp16 q/k/v ----------------
__global__ void qkvg_kernel(const float* __restrict__ wq, const float* __restrict__ bq,
                            const float* __restrict__ wk, const float* __restrict__ wv,
                            const float* __restrict__ wg) {
    __shared__ float h_sh[8 * CA];
    int r0 = blockIdx.x * 8;
    int tid = threadIdx.x;
    int cp = tid & 63, rg = tid >> 6;
    #pragma unroll
    for (int i = 0; i < 4; i++) {
        int idx = tid + i * 256;
        h_sh[idx] = g_h[(size_t)r0 * CA + idx];
    }
    __syncthreads();
    const u64* wA2 = (const u64*)((blockIdx.y == 0) ? wq : wk);
    const u64* wB2 = (const u64*)((blockIdx.y == 0) ? wg : wv);
    u64 aA[2] = {0, 0}, aB[2] = {0, 0};
    #pragma unroll 8
    for (int j = 0; j < CA; j++) {
        u64 w1 = wA2[j * 64 + cp];
        u64 w2 = wB2[j * 64 + cp];
        float h0 = h_sh[(2 * rg + 0) * CA + j];
        float h1 = h_sh[(2 * rg + 1) * CA + j];
        u64 s0 = pk2(h0, h0), s1 = pk2(h1, h1);
        aA[0] = f2fma(s0, w1, aA[0]);
        aA[1] = f2fma(s1, w1, aA[1]);
        aB[0] = f2fma(s0, w2, aB[0]);
        aB[1] = f2fma(s1, w2, aB[1]);
    }
    if (blockIdx.y == 0) {
        const float qscale = 0.17677669529663687f * LOG2E;  // 1/sqrt(32) * log2e
        float b0 = bq[2 * cp], b1 = bq[2 * cp + 1];
        #pragma unroll
        for (int rr = 0; rr < 2; rr++) {
            int row = r0 + 2 * rg + rr;
            float x0, x1, y0, y1;
            upk2(aA[rr], x0, x1);
            upk2(aB[rr], y0, y1);
            ((__half2*)g_qh)[(size_t)row * 64 + cp] =
                __floats2half2_rn((x0 + b0) * qscale, (x1 + b1) * qscale);
            float2 g; g.x = sigmoidf_(y0); g.y = sigmoidf_(y1);
            ((float2*)g_g)[(size_t)row * 64 + cp] = g;
        }
    } else {
        #pragma unroll
        for (int rr = 0; rr < 2; rr++) {
            int row = r0 + 2 * rg + rr;
            float x0, x1, y0, y1;
            upk2(aA[rr], x0, x1);
            upk2(aB[rr], y0, y1);
            ((__half2*)g_kh)[(size_t)row * 64 + cp] = __floats2half2_rn(x0, x1);
            ((__half2*)g_vh)[(size_t)row * 64 + cp] = __floats2half2_rn(y0, y1);
        }
    }
}

// ---------------- V transpose ----------------
__global__ void vt_kernel() {
    __shared__ __half vsh[32 * KSTRH];
    int tid = threadIdx.x;  // 256
    int t0 = blockIdx.x * 32;
    #pragma unroll
    for (int i = 0; i < 2; i++) {
        int c = tid + i * 256;
        int row = c >> 4, part = c & 15;
        *(uint4*)&vsh[row * KSTRH + part * 8] =
            *(const uint4*)&g_vh[(size_t)(t0 + row) * CA + part * 8];
    }
    __syncthreads();
    #pragma unroll
    for (int i = 0; i < 2; i++) {
        int c = tid + i * 256;
        int ch = c & 127, grp = c >> 7;
        __half tmp[8];
        #pragma unroll
        for (int j = 0; j < 8; j++) tmp[j] = vsh[(grp * 8 + j) * KSTRH + ch];
        *(uint4*)&g_vt[(size_t)ch * NN + t0 + grp * 8] = *(uint4*)tmp;
    }
}

// ---------------- Attention: fp16 mma, split-K, 3-stage cp.async pipeline ----------------
__global__ void __launch_bounds__(ATHREADS, 2)
attn_kernel() {
    extern __shared__ __half smh[];
    __half* k_sh = smh;                              // NSTG*32*KSTRH
    __half* vt_sh = k_sh + NSTG * 32 * KSTRH;        // NSTG*128*VSTRH
    __half* b_sh = vt_sh + NSTG * 128 * VSTRH;       // NSTG*128*BSTRH
    __half* p_sh = b_sh + NSTG * 128 * BSTRH;        // 8*16*PSTRH (Q overlay)

    int tid = threadIdx.x;
    int q0 = blockIdx.x * TQ;
    int kbase = blockIdx.y * KPS;

    auto issue_tile = [&](int k0, int buf) {
        #pragma unroll
        for (int i = 0; i < 2; i++) {
            int c = tid + i * 256;
            { int row = c >> 4, part = c & 15;
              cpa16(&k_sh[buf * 32 * KSTRH + row * KSTRH + part * 8],
                    &g_kh[(size_t)(k0 + row) * CA + part * 8]); }
            { int ch = c >> 2, part = c & 3;
              cpa16(&vt_sh[buf * 128 * VSTRH + ch * VSTRH + part * 8],
                    &g_vt[(size_t)ch * NN + k0 + part * 8]); }
            { int row = c >> 2, part = c & 3;
              int hh = row >> 5, qq = row & 31;
              cpa16(&b_sh[buf * 128 * BSTRH + row * BSTRH + part * 8],
                    &g_bias[((size_t)hh * NN + (q0 + qq)) * NN + k0 + part * 8]); }
        }
    };

    // prologue: tiles 0 and 1 in flight
    issue_tile(kbase, 0);
    CPA_COMMIT();
    issue_tile(kbase + TK, 1);
    CPA_COMMIT();

    // stage Q into p overlay
    #pragma unroll
    for (int i = 0; i < 2; i++) {
        int c = tid + i * 256;
        int row = c >> 4, part = c & 15;
        *(uint4*)&p_sh[row * KSTRH + part * 8] =
            *(const uint4*)&g_qh[(size_t)(q0 + row) * CA + part * 8];
    }
    __syncthreads();

    int warp = tid >> 5, lane = tid & 31;
    int h = warp & 3;
    int qg = warp >> 2;
    int g = lane >> 2;
    int t4 = lane & 3;
    int rowg = qg * 16 + g;

    uint32_t pB = (uint32_t)__cvta_generic_to_shared(p_sh);
    uint32_t kB = (uint32_t)__cvta_generic_to_shared(k_sh);
    uint32_t vB = (uint32_t)__cvta_generic_to_shared(vt_sh);
    uint32_t bB = (uint32_t)__cvta_generic_to_shared(b_sh);

    uint32_t qa[2][4];
    #pragma unroll
    for (int dc = 0; dc < 2; dc++) {
        uint32_t base  = pB + ((rowg)     * KSTRH + h * 32 + dc * 16 + 2 * t4) * 2;
        uint32_t base8 = pB + ((rowg + 8) * KSTRH + h * 32 + dc * 16 + 2 * t4) * 2;
        qa[dc][0] = lds32(base);
        qa[dc][1] = lds32(base8);
        qa[dc][2] = lds32(base + 16);
        qa[dc][3] = lds32(base8 + 16);
    }
    __syncthreads();   // overlay becomes p_sh

    uint32_t pw = pB + warp * 16 * PSTRH * 2;

    float m0 = -1e30f, m1 = -1e30f, l0 = 0.f, l1 = 0.f;
    float o[4][4];
    #pragma unroll
    for (int nb = 0; nb < 4; nb++)
        #pragma unroll
        for (int i = 0; i < 4; i++) o[nb][i] = 0.f;

    for (int t = 0; t < NT; t++) {
        CPA_WAIT1();            // group t complete (group t+1 may remain in flight)
        __syncthreads();        // all warps done with tile t-1

        if (t + 2 < NT) issue_tile(kbase + (t + 2) * TK, (t + 2) % NSTG);
        CPA_COMMIT();           // empty groups keep wait_group accounting uniform

        int bi = t % NSTG;
        uint32_t kbuf = kB + bi * 32 * KSTRH * 2;
        uint32_t vbuf = vB + bi * 128 * VSTRH * 2;
        uint32_t bbuf = bB + bi * 128 * BSTRH * 2;

        // QK^T mma, bias-initialized C (base-2 domain)
        float c[4][4];
        #pragma unroll
        for (int kb = 0; kb < 4; kb++) {
            uint32_t x01 = lds32(bbuf + ((h * 32 + rowg)     * BSTRH + kb * 8 + 2 * t4) * 2);
            uint32_t x23 = lds32(bbuf + ((h * 32 + rowg + 8) * BSTRH + kb * 8 + 2 * t4) * 2);
            float2 f01 = __half22float2(*(__half2*)&x01);
            float2 f23 = __half22float2(*(__half2*)&x23);
            c[kb][0] = f01.x; c[kb][1] = f01.y;
            c[kb][2] = f23.x; c[kb][3] = f23.y;
        }
        #pragma unroll
        for (int dc = 0; dc < 2; dc++) {
            #pragma unroll
            for (int kb = 0; kb < 4; kb++) {
                uint32_t base = kbuf + ((kb * 8 + g) * KSTRH + h * 32 + dc * 16 + 2 * t4) * 2;
                uint32_t b0 = lds32(base);
                uint32_t b1 = lds32(base + 16);
                mmaf16(c[kb], qa[dc], b0, b1);
            }
        }

        // online softmax (base-2)
        float v0[8] = {c[0][0], c[0][1], c[1][0], c[1][1], c[2][0], c[2][1], c[3][0], c[3][1]};
        float v1[8] = {c[0][2], c[0][3], c[1][2], c[1][3], c[2][2], c[2][3], c[3][2], c[3][3]};
        float mx0 = v0[0], mx1 = v1[0];
        #pragma unroll
        for (int i = 1; i < 8; i++) { mx0 = fmaxf(mx0, v0[i]); mx1 = fmaxf(mx1, v1[i]); }
        mx0 = fmaxf(mx0, __shfl_xor_sync(0xffffffffu, mx0, 1));
        mx0 = fmaxf(mx0, __shfl_xor_sync(0xffffffffu, mx0, 2));
        mx1 = fmaxf(mx1, __shfl_xor_sync(0xffffffffu, mx1, 1));
        mx1 = fmaxf(mx1, __shfl_xor_sync(0xffffffffu, mx1, 2));
        float mn0 = fmaxf(m0, mx0), mn1 = fmaxf(m1, mx1);
        float sum0 = 0.f, sum1 = 0.f;
        #pragma unroll
        for (int i = 0; i < 8; i++) {
            v0[i] = ex2_(v0[i] - mn0); sum0 += v0[i];
            v1[i] = ex2_(v1[i] - mn1); sum1 += v1[i];
        }
        sum0 += __shfl_xor_sync(0xffffffffu, sum0, 1);
        sum0 += __shfl_xor_sync(0xffffffffu, sum0, 2);
        sum1 += __shfl_xor_sync(0xffffffffu, sum1, 1);
        sum1 += __shfl_xor_sync(0xffffffffu, sum1, 2);
        float scl0 = ex2_(m0 - mn0), scl1 = ex2_(m1 - mn1);
        l0 = l0 * scl0 + sum0; m0 = mn0;
        l1 = l1 * scl1 + sum1; m1 = mn1;

        // store P (fp16)
        #pragma unroll
        for (int kb = 0; kb < 4; kb++) {
            __half2 h0 = __floats2half2_rn(v0[2 * kb], v0[2 * kb + 1]);
            __half2 h1 = __floats2half2_rn(v1[2 * kb], v1[2 * kb + 1]);
            sts32(pw + ((g)     * PSTRH + kb * 8 + 2 * t4) * 2, *(uint32_t*)&h0);
            sts32(pw + ((g + 8) * PSTRH + kb * 8 + 2 * t4) * 2, *(uint32_t*)&h1);
        }
        __syncwarp();

        // rescale O
        #pragma unroll
        for (int nb = 0; nb < 4; nb++) {
            o[nb][0] *= scl0; o[nb][1] *= scl0;
            o[nb][2] *= scl1; o[nb][3] *= scl1;
        }

        // P @ V
        #pragma unroll
        for (int kc = 0; kc < 2; kc++) {
            uint32_t pa[4];
            pa[0] = lds32(pw + ((g)     * PSTRH + kc * 16 + 2 * t4) * 2);
            pa[1] = lds32(pw + ((g + 8) * PSTRH + kc * 16 + 2 * t4) * 2);
            pa[2] = lds32(pw + ((g)     * PSTRH + kc * 16 + 2 * t4 + 8) * 2);
            pa[3] = lds32(pw + ((g + 8) * PSTRH + kc * 16 + 2 * t4 + 8) * 2);
            #pragma unroll
            for (int nb = 0; nb < 4; nb++) {
                uint32_t vb = vbuf + ((h * 32 + nb * 8 + g) * VSTRH + kc * 16 + 2 * t4) * 2;
                uint32_t b0 = lds32(vb);
                uint32_t b1 = lds32(vb + 16);
                mmaf16(o[nb], pa, b0, b1);
            }
        }
        __syncwarp();
    }

    // epilogue: normalized fp16 partials
    size_t sp = blockIdx.y;
    float il0 = 1.f / l0, il1 = 1.f / l1;
    __half2* poh = (__half2*)g_po;
    #pragma unroll
    for (int nb = 0; nb < 4; nb++) {
        int q_a = q0 + rowg, q_b = q0 + rowg + 8;
        poh[(sp * NN + q_a) * 64 + h * 16 + nb * 4 + t4] =
            __floats2half2_rn(o[nb][0] * il0, o[nb][1] * il0);
        poh[(sp * NN + q_b) * 64 + h * 16 + nb * 4 + t4] =
            __floats2half2_rn(o[nb][2] * il1, o[nb][3] * il1);
    }
    if (t4 == 0) {
        int q_a = q0 + rowg, q_b = q0 + rowg + 8;
        g_pm[(sp * NN + q_a) * NH + h] = m0;
        g_pl[(sp * NN + q_a) * NH + h] = l0;
        g_pm[(sp * NN + q_b) * NH + h] = m1;
        g_pl[(sp * NN + q_b) * NH + h] = l1;
    }
}

// ---------------- split-K combine (base-2 weights, fp16 partials) ----------------
__global__ void combine_kernel() {
    int tid = threadIdx.x;               // 256
    int q = blockIdx.x * 2 + (tid >> 7);
    int hd = tid & 127;
    int h = hd >> 5;
    float ms[NSPLIT];
    float M = -1e30f;
    #pragma unroll
    for (int s = 0; s < NSPLIT; s++) {
        ms[s] = g_pm[((size_t)s * NN + q) * NH + h];
        M = fmaxf(M, ms[s]);
    }
    float osum = 0.f, lsum = 0.f;
    #pragma unroll
    for (int s = 0; s < NSPLIT; s++) {
        float w = ex2_(ms[s] - M);
        float lw = g_pl[((size_t)s * NN + q) * NH + h];
        lsum = fmaf(w, lw, lsum);
        osum = fmaf(w * lw, __half2float(g_po[((size_t)s * NN + q) * CA + hd]), osum);
    }
    g_o[(size_t)q * CA + hd] = osum / lsum;
}

// ---------------- fused: output proj + gate + residual1 + LN + AdaLN2; 8 rows, 256 thr ----------------
__global__ void post_kernel(const float* __restrict__ wo,
                            const float* __restrict__ s,
                            const float* __restrict__ sg1w,
                            const float* __restrict__ sg1b,
                            const float* __restrict__ a,
                            const float* __restrict__ a2sw,
                            const float* __restrict__ a2scw,
                            const float* __restrict__ a2shw,
                            const float* __restrict__ a2scb) {
    __shared__ float go_sh[8 * CA];    // later reused as an2
    __shared__ float s_sh[8 * CS];     // raw s, later reused as sn2
    __shared__ float r1_sh[8 * CA];
    int r0 = blockIdx.x * 8;
    int tid = threadIdx.x;
    int warp = tid >> 5, lane = tid & 31;
    int cp = tid & 63, rg = tid >> 6;

    #pragma unroll
    for (int i = 0; i < 4; i++) {
        int idx = tid + i * 256;
        go_sh[idx] = g_g[(size_t)r0 * CA + idx] * g_o[(size_t)r0 * CA + idx];
    }
    #pragma unroll
    for (int i = 0; i < 12; i++) {
        int idx = tid + i * 256;
        s_sh[idx] = s[(size_t)r0 * CS + idx];
    }
    __syncthreads();

    // matvec 1: wo (CA-K) and sg1w (CS-K); rows 2rg, 2rg+1
    {
        const u64* wo2 = (const u64*)wo;
        const u64* sg2 = (const u64*)sg1w;
        u64 aA[2] = {0, 0};
        #pragma unroll 8
        for (int j = 0; j < CA; j++) {
            u64 w = wo2[j * 64 + cp];
            float g0 = go_sh[(2 * rg + 0) * CA + j];
            float g1 = go_sh[(2 * rg + 1) * CA + j];
            aA[0] = f2fma(pk2(g0, g0), w, aA[0]);
            aA[1] = f2fma(pk2(g1, g1), w, aA[1]);
        }
        u64 aG[2] = {0, 0};
        #pragma unroll 4
        for (int j = 0; j < CS; j++) {
            u64 w = sg2[j * 64 + cp];
            float s0 = s_sh[(2 * rg + 0) * CS + j];
            float s1 = s_sh[(2 * rg + 1) * CS + j];
            aG[0] = f2fma(pk2(s0, s0), w, aG[0]);
            aG[1] = f2fma(pk2(s1, s1), w, aG[1]);
        }
        float gb0 = sg1b[2 * cp], gb1 = sg1b[2 * cp + 1];
        #pragma unroll
        for (int rr = 0; rr < 2; rr++) {
            int row = r0 + 2 * rg + rr;
            float x0, x1, y0, y1;
            upk2(aA[rr], x0, x1);
            upk2(aG[rr], y0, y1);
            float2 av = ((const float2*)a)[(size_t)row * 64 + cp];
            float2 o;
            o.x = sigmoidf_(y0 + gb0) * x0 + av.x;
            o.y = sigmoidf_(y1 + gb1) * x1 + av.y;
            ((float2*)g_r1)[(size_t)row * 64 + cp] = o;
            *(float2*)&r1_sh[(2 * rg + rr) * CA + 2 * cp] = o;
        }
    }
    __syncthreads();

    // LN(r1): warp per row -> go_sh (now an2)
    {
        float4 va = *(float4*)&r1_sh[warp * CA + lane * 4];
        float sum = va.x + va.y + va.z + va.w;
        float ss = fmaf(va.x, va.x, fmaf(va.y, va.y, fmaf(va.z, va.z, va.w * va.w)));
        sum = wredsum(sum); ss = wredsum(ss);
        float mean = sum * (1.f / CA);
        float var = fmaf(-mean, mean, ss * (1.f / CA));
        float rs = rsqrtf(var + LNEPS);
        float4 o;
        o.x = (va.x - mean) * rs; o.y = (va.y - mean) * rs;
        o.z = (va.z - mean) * rs; o.w = (va.w - mean) * rs;
        *(float4*)&go_sh[warp * CA + lane * 4] = o;
    }
    // reload s_sh as LN(s)*s_w2
    #pragma unroll
    for (int i = 0; i < 12; i++) {
        int idx = tid + i * 256;
        s_sh[idx] = g_sn[(size_t)r0 * CS + idx] * a2sw[idx % CS];
    }
    __syncthreads();

    // matvec 2: AdaLN2
    {
        const u64* sw2 = (const u64*)a2scw;
        const u64* hw2 = (const u64*)a2shw;
        u64 a1[2] = {0, 0}, a2[2] = {0, 0};
        #pragma unroll 4
        for (int j = 0; j < CS; j++) {
            u64 w1 = sw2[j * 64 + cp];
            u64 w2 = hw2[j * 64 + cp];
            float sv0 = s_sh[(2 * rg + 0) * CS + j];
            float sv1 = s_sh[(2 * rg + 1) * CS + j];
            u64 s0 = pk2(sv0, sv0), s1 = pk2(sv1, sv1);
            a1[0] = f2fma(s0, w1, a1[0]);
            a1[1] = f2fma(s1, w1, a1[1]);
            a2[0] = f2fma(s0, w2, a2[0]);
            a2[1] = f2fma(s1, w2, a2[1]);
        }
        float sb0 = a2scb[2 * cp], sb1 = a2scb[2 * cp + 1];
        #pragma unroll
        for (int rr = 0; rr < 2; rr++) {
            int row = r0 + 2 * rg + rr;
            float x0, x1, y0, y1;
            upk2(a1[rr], x0, x1);
            upk2(a2[rr], y0, y1);
            float2 anv = *(float2*)&go_sh[(2 * rg + rr) * CA + 2 * cp];
            float2 o;
            o.x = sigmoidf_(x0 + sb0) * anv.x + y0;
            o.y = sigmoidf_(x1 + sb1) * anv.y + y1;
            ((float2*)g_h2)[(size_t)row * 64 + cp] = o;
        }
    }
}

// ---------------- SwiGLU FFN + gate + residual 2; 8 rows, 256 thr ----------------
__global__ void ffn_kernel(const float* __restrict__ w1, const float* __restrict__ w2,
                           const float* __restrict__ wout,
                           const float* __restrict__ s,
                           const float* __restrict__ sg2w, const float* __restrict__ sg2b,
                           float* __restrict__ out) {
    __shared__ float h_sh[8 * CA];
    __shared__ float s_sh[8 * CS];
    __shared__ __align__(16) float gt_sh[8 * CF];
    int r0 = blockIdx.x * 8;
    int tid = threadIdx.x;   // 256
    #pragma unroll
    for (int i = 0; i < 4; i++) {
        int idx = tid + i * 256;
        h_sh[idx] = g_h2[(size_t)r0 * CA + idx];
    }
    #pragma unroll
    for (int i = 0; i < 12; i++) {
        int idx = tid + i * 256;
        s_sh[idx] = s[(size_t)r0 * CS + idx];
    }
    __syncthreads();
    {
        int cpf = tid & 127, rgf = tid >> 7;   // rgf 0..1 -> rows rgf*4..rgf*4+3
        const u64* w1p = (const u64*)w1;
        const u64* w2p = (const u64*)w2;
        u64 u1[4] = {0, 0, 0, 0}, u2[4] = {0, 0, 0, 0};
        #pragma unroll 4
        for (int j = 0; j < CA; j++) {
            u64 wa = w1p[j * 128 + cpf];
            u64 wbv = w2p[j * 128 + cpf];
            #pragma unroll
            for (int rr = 0; rr < 4; rr++) {
                float hv = h_sh[(rgf * 4 + rr) * CA + j];
                u64 sv = pk2(hv, hv);
                u1[rr] = f2fma(sv, wa, u1[rr]);
                u2[rr] = f2fma(sv, wbv, u2[rr]);
            }
        }
        #pragma unroll
        for (int rr = 0; rr < 4; rr++) {
            float x0, x1, y0, y1;
            upk2(u1[rr], x0, x1);
            upk2(u2[rr], y0, y1);
            float g0 = (x0 * sigmoidf_(x0)) * y0;
            float g1 = (x1 * sigmoidf_(x1)) * y1;
            ((u64*)gt_sh)[(rgf * 4 + rr) * 128 + cpf] = pk2(g0, g1);
        }
    }
    __syncthreads();
    {
        int cp = tid & 63, rw = tid >> 6;      // rw 0..3 -> rows 2rw, 2rw+1
        const u64* wop = (const u64*)wout;
        const u64* sgp = (const u64*)sg2w;
        u64 aF[2] = {0, 0}, aG[2] = {0, 0};
        #pragma unroll 8
        for (int j = 0; j < CF; j++) {
            u64 w = wop[j * 64 + cp];
            float g0 = gt_sh[(2 * rw + 0) * CF + j];
            float g1 = gt_sh[(2 * rw + 1) * CF + j];
            aF[0] = f2fma(pk2(g0, g0), w, aF[0]);
            aF[1] = f2fma(pk2(g1, g1), w, aF[1]);
        }
        #pragma unroll 4
        for (int j = 0; j < CS; j++) {
            u64 w = sgp[j * 64 + cp];
            float s0 = s_sh[(2 * rw + 0) * CS + j];
            float s1 = s_sh[(2 * rw + 1) * CS + j];
            aG[0] = f2fma(pk2(s0, s0), w, aG[0]);
            aG[1] = f2fma(pk2(s1, s1), w, aG[1]);
        }
        float gb0 = sg2b[2 * cp], gb1 = sg2b[2 * cp + 1];
        #pragma unroll
        for (int rr = 0; rr < 2; rr++) {
            int row = r0 + 2 * rw + rr;
            float f0, f1, gg0, gg1;
            upk2(aF[rr], f0, f1);
            upk2(aG[rr], gg0, gg1);
            float2 rv = ((const float2*)g_r1)[(size_t)row * 64 + cp];
            float2 o;
            o.x = sigmoidf_(gg0 + gb0) * f0 + rv.x;
            o.y = sigmoidf_(gg1 + gb1) * f1 + rv.y;
            ((float2*)out)[(size_t)row * 64 + cp] = o;
        }
    }
}

// ---------------- launch ----------------
extern "C" void kernel_launch(void* const* d_in, const int* in_sizes, int n_in,
                              void* d_out, int out_size) {
    const float* a      = (const float*)d_in[0];
    const float* s      = (const float*)d_in[1];
    const float* z      = (const float*)d_in[2];
    const float* a1sw   = (const float*)d_in[3];
    const float* a1scw  = (const float*)d_in[4];
    const float* a1scb  = (const float*)d_in[5];
    const float* a1shw  = (const float*)d_in[6];
    const float* wq     = (const float*)d_in[7];
    const float* bq     = (const float*)d_in[8];
    const float* wk     = (const float*)d_in[9];
    const float* wv     = (const float*)d_in[10];
    const float* lnzw   = (const float*)d_in[11];
    const float* lnzb   = (const float*)d_in[12];
    const float* wb     = (const float*)d_in[13];
    const float* wg     = (const float*)d_in[14];
    const float* wo     = (const float*)d_in[15];
    const float* sg1w   = (const float*)d_in[16];
    const float* sg1b   = (const float*)d_in[17];
    const float* a2sw   = (const float*)d_in[18];
    const float* a2scw  = (const float*)d_in[19];
    const float* a2scb  = (const float*)d_in[20];
    const float* a2shw  = (const float*)d_in[21];
    const float* w1     = (const float*)d_in[22];
    const float* w2     = (const float*)d_in[23];
    const float* wout   = (const float*)d_in[24];
    const float* sg2w   = (const float*)d_in[25];
    const float* sg2b   = (const float*)d_in[26];
    float* out = (float*)d_out;

    const int ATTN_SMEM =
        (NSTG * 32 * KSTRH + NSTG * 128 * VSTRH + NSTG * 128 * BSTRH + 8 * 16 * PSTRH) * 2;
    static int attrset = 0;
    if (!attrset) {
        cudaFuncSetAttribute(attn_kernel, cudaFuncAttributeMaxDynamicSharedMemorySize, ATTN_SMEM);
        attrset = 1;
    }

    bias_kernel<<<dim3(NN / 8, NN / 32), 256>>>(z, lnzw, lnzb, wb);
    adaln1_kernel<<<NN / 8, 256>>>(a, s, a1sw, a1scw, a1shw, a1scb);
    qkvg_kernel<<<dim3(NN / 8, 2), 256>>>(wq, bq, wk, wv, wg);
    vt_kernel<<<NN / 32, 256>>>();
    attn_kernel<<<dim3(NN / TQ, NSPLIT), ATHREADS, ATTN_SMEM>>>();
    combine_kernel<<<NN / 2, 256>>>();
    post_kernel<<<NN / 8, 256>>>(wo, s, sg1w, sg1b, a, a2sw, a2scw, a2shw, a2scb);
    ffn_kernel<<<NN / 8, 256>>>(w1, w2, wout, s, sg2w, sg2b, out);
    (void)in_sizes; (void)n_in; (void)out_size;
}